// round 12
// baseline (speedup 1.0000x reference)
#include <cuda_runtime.h>

#define C 32
#define BMAX 16
#define EPS 1e-5f

// Scratch (device globals: zero-initialized at module load; finalize_kernel
// resets them after consuming, so every graph replay starts clean).
__device__ float g_sum[BMAX * C];
__device__ float g_sq[BMAX * C];
__device__ float g_cnt[BMAX];
__device__ float g_scale[BMAX * C];
__device__ float g_shift[BMAX * C];

// ---------------------------------------------------------------------------
// Warp-cooperative accumulation of one single-segment run [rs, re).
// Lane L loads the float4 at column (L&7), row offset (L>>3): a warp
// consumes 4 rows per LDG.128. 8-row main loop, one-chunk lookahead
// (2 live float4 prefetches) — deliberately SHALLOW to keep regs <= 42 so
// 6 blocks/SM fit: R11 showed reduce scales with resident warps, not MLP.
// ---------------------------------------------------------------------------
__device__ __forceinline__ void accum_run(const float* __restrict__ data,
                                          int rs, int re, int b, int lane) {
    int rows = re - rs;
    if (rows <= 0) return;
    int sub = lane & 7;        // float4 column (channels sub*4 .. sub*4+3)
    int rg  = lane >> 3;       // row offset within 4-row group

    const float4* base = reinterpret_cast<const float4*>(
        data + (size_t)rs * C) + (size_t)rg * 8 + sub;

    float4 s = make_float4(0.f, 0.f, 0.f, 0.f);
    float4 q = make_float4(0.f, 0.f, 0.f, 0.f);

    #define ACC(v)                                                   \
        s.x += (v).x; s.y += (v).y; s.z += (v).z; s.w += (v).w;      \
        q.x = fmaf((v).x, (v).x, q.x); q.y = fmaf((v).y, (v).y, q.y);\
        q.z = fmaf((v).z, (v).z, q.z); q.w = fmaf((v).w, (v).w, q.w)

    int nch = rows >> 3;               // full 8-row chunks
    int r = nch << 3;
    if (nch > 0) {
        float4 a = base[0];
        float4 c = base[32];
        for (int k = 1; k < nch; ++k) {
            const float4* p = base + (size_t)k * 64;
            float4 a2 = p[0];          // prefetch chunk k
            float4 c2 = p[32];
            ACC(a); ACC(c);
            a = a2; c = c2;
        }
        ACC(a); ACC(c);
    }
    if (r + 4 <= rows) {
        float4 a = base[(size_t)r * 8];
        ACC(a);
        r += 4;
    }
    if (r < rows && r + rg < rows) {   // 1-3 remaining rows, predicated
        float4 a = base[(size_t)r * 8];
        ACC(a);
    }
    #undef ACC

    // Combine lanes sharing the same channels (rg = 0..3): xor 16, 8.
    #pragma unroll
    for (int off = 16; off >= 8; off >>= 1) {
        s.x += __shfl_xor_sync(0xffffffffu, s.x, off);
        s.y += __shfl_xor_sync(0xffffffffu, s.y, off);
        s.z += __shfl_xor_sync(0xffffffffu, s.z, off);
        s.w += __shfl_xor_sync(0xffffffffu, s.w, off);
        q.x += __shfl_xor_sync(0xffffffffu, q.x, off);
        q.y += __shfl_xor_sync(0xffffffffu, q.y, off);
        q.z += __shfl_xor_sync(0xffffffffu, q.z, off);
        q.w += __shfl_xor_sync(0xffffffffu, q.w, off);
    }

    if (rg == 0) {   // lanes 0..7 flush channels sub*4 .. sub*4+3
        int b4 = b * C + sub * 4;
        atomicAdd(&g_sum[b4 + 0], s.x);
        atomicAdd(&g_sum[b4 + 1], s.y);
        atomicAdd(&g_sum[b4 + 2], s.z);
        atomicAdd(&g_sum[b4 + 3], s.w);
        atomicAdd(&g_sq[b4 + 0], q.x);
        atomicAdd(&g_sq[b4 + 1], q.y);
        atomicAdd(&g_sq[b4 + 2], q.z);
        atomicAdd(&g_sq[b4 + 3], q.w);
    }
    if (lane == 0) atomicAdd(&g_cnt[b], (float)rows);
}

// ---------------------------------------------------------------------------
// Kernel 1: per-segment sum / sumsq / count.
// __launch_bounds__(256, 6): cap regs so 6 blocks/SM (48 warps) fit —
// occupancy, not per-warp MLP, is the measured binder (R11 ncu).
// ---------------------------------------------------------------------------
__global__ void __launch_bounds__(256, 6)
reduce_kernel(const float* __restrict__ data,
              const int* __restrict__ bid,
              int N, int rows_per_warp) {
    int warp = (int)((blockIdx.x * blockDim.x + threadIdx.x) >> 5);
    int lane = threadIdx.x & 31;

    int r0 = warp * rows_per_warp;
    if (r0 >= N) return;
    int r1 = r0 + rows_per_warp;
    if (r1 > N) r1 = N;

    int b_first = bid[r0];
    int b_last = bid[r1 - 1];

    if (b_first == b_last) {
        accum_run(data, r0, r1, b_first, lane);
    } else {
        int r = r0;
        int b = b_first;
        while (r < r1) {
            int lo = r + 1, hi = r1;
            while (lo < hi) {                 // binary search run end
                int mid = (lo + hi) >> 1;     // broadcast load
                if (bid[mid] == b) lo = mid + 1;
                else hi = mid;
            }
            accum_run(data, r, lo, b, lane);
            r = lo;
            if (r < r1) b = bid[r];
        }
    }
}

// ---------------------------------------------------------------------------
// Kernel 2: fold stats into per-(b,c) scale/shift, THEN reset the
// accumulators to zero so the next graph replay starts clean.
// ---------------------------------------------------------------------------
__global__ void finalize_kernel(const float* __restrict__ w,
                                const float* __restrict__ bias) {
    int i = threadIdx.x;           // 0..BMAX*C-1
    if (i >= BMAX * C) return;
    int b = i / C, c = i % C;
    float cnt = g_cnt[b];
    float norm = 1.0f / (cnt + EPS);
    float sum = g_sum[i];
    float mean = sum * norm;
    float var = (g_sq[i] - 2.0f * mean * sum + mean * mean * cnt) * norm;
    float inv_std = rsqrtf(var + EPS);
    float wc = w ? w[c] : 1.0f;
    float bc = bias ? bias[c] : 0.0f;
    float sc = inv_std * wc;
    g_scale[i] = sc;
    g_shift[i] = bc - mean * sc;
    // Consume-and-reset for the next replay.
    g_sum[i] = 0.0f;
    g_sq[i] = 0.0f;
    if (c == 0) g_cnt[b] = 0.0f;
}

// ---------------------------------------------------------------------------
// Normalize one single-segment run [rs, re): scale/shift in registers
// (loaded once per run), inner loop pure LDG.128 -> FMA -> STG.128 with
// one-chunk lookahead.  [R10: 6.4 TB/s effective — at ceiling, unchanged]
// ---------------------------------------------------------------------------
__device__ __forceinline__ void norm_run(const float* __restrict__ data,
                                         float* __restrict__ out,
                                         const float4* s_scale,
                                         const float4* s_shift,
                                         int rs, int re, int b, int lane) {
    int rows = re - rs;
    if (rows <= 0) return;
    int sub = lane & 7;
    int rg  = lane >> 3;

    float4 sc = s_scale[b * 8 + sub];   // once per run
    float4 sh = s_shift[b * 8 + sub];

    const float4* pi = reinterpret_cast<const float4*>(
        data + (size_t)rs * C) + (size_t)rg * 8 + sub;
    float4* po = reinterpret_cast<float4*>(
        out + (size_t)rs * C) + (size_t)rg * 8 + sub;

    int nch = rows >> 3;               // full 8-row chunks
    int r = nch << 3;
    if (nch > 0) {
        float4 a = __ldcs(pi);
        float4 c = __ldcs(pi + 32);
        for (int k = 1; k < nch; ++k) {
            const float4* p = pi + (size_t)k * 64;
            float4 a2 = __ldcs(p);         // prefetch chunk k
            float4 c2 = __ldcs(p + 32);
            float4 o0, o1;
            o0.x = fmaf(a.x, sc.x, sh.x); o0.y = fmaf(a.y, sc.y, sh.y);
            o0.z = fmaf(a.z, sc.z, sh.z); o0.w = fmaf(a.w, sc.w, sh.w);
            o1.x = fmaf(c.x, sc.x, sh.x); o1.y = fmaf(c.y, sc.y, sh.y);
            o1.z = fmaf(c.z, sc.z, sh.z); o1.w = fmaf(c.w, sc.w, sh.w);
            float4* po_k = po + (size_t)(k - 1) * 64;
            __stcs(po_k, o0);
            __stcs(po_k + 32, o1);
            a = a2; c = c2;
        }
        float4 o0, o1;
        o0.x = fmaf(a.x, sc.x, sh.x); o0.y = fmaf(a.y, sc.y, sh.y);
        o0.z = fmaf(a.z, sc.z, sh.z); o0.w = fmaf(a.w, sc.w, sh.w);
        o1.x = fmaf(c.x, sc.x, sh.x); o1.y = fmaf(c.y, sc.y, sh.y);
        o1.z = fmaf(c.z, sc.z, sh.z); o1.w = fmaf(c.w, sc.w, sh.w);
        float4* po_k = po + (size_t)(nch - 1) * 64;
        __stcs(po_k, o0);
        __stcs(po_k + 32, o1);
    }
    if (r + 4 <= rows) {
        float4 a = __ldcs(pi + (size_t)r * 8);
        float4 o;
        o.x = fmaf(a.x, sc.x, sh.x); o.y = fmaf(a.y, sc.y, sh.y);
        o.z = fmaf(a.z, sc.z, sh.z); o.w = fmaf(a.w, sc.w, sh.w);
        __stcs(po + (size_t)r * 8, o);
        r += 4;
    }
    if (r < rows && r + rg < rows) {   // 1-3 remaining rows, predicated
        float4 a = __ldcs(pi + (size_t)r * 8);
        float4 o;
        o.x = fmaf(a.x, sc.x, sh.x); o.y = fmaf(a.y, sc.y, sh.y);
        o.z = fmaf(a.z, sc.z, sh.z); o.w = fmaf(a.w, sc.w, sh.w);
        __stcs(po + (size_t)r * 8, o);
    }
}

// ---------------------------------------------------------------------------
// Kernel 3: normalize, warp-chunked like the reduce.
// ---------------------------------------------------------------------------
__global__ void normalize_kernel(const float* __restrict__ data,
                                 const int* __restrict__ bid,
                                 float* __restrict__ out,
                                 int N, int rows_per_warp) {
    __shared__ float4 s_scale[BMAX * C / 4];
    __shared__ float4 s_shift[BMAX * C / 4];
    for (int i = threadIdx.x; i < BMAX * C / 4; i += blockDim.x) {
        s_scale[i] = reinterpret_cast<const float4*>(g_scale)[i];
        s_shift[i] = reinterpret_cast<const float4*>(g_shift)[i];
    }
    __syncthreads();

    int warp = (int)((blockIdx.x * blockDim.x + threadIdx.x) >> 5);
    int lane = threadIdx.x & 31;

    int r0 = warp * rows_per_warp;
    if (r0 >= N) return;
    int r1 = r0 + rows_per_warp;
    if (r1 > N) r1 = N;

    int b_first = bid[r0];
    int b_last = bid[r1 - 1];

    if (b_first == b_last) {
        norm_run(data, out, s_scale, s_shift, r0, r1, b_first, lane);
    } else {
        int r = r0;
        int b = b_first;
        while (r < r1) {
            int lo = r + 1, hi = r1;
            while (lo < hi) {
                int mid = (lo + hi) >> 1;     // broadcast load
                if (bid[mid] == b) lo = mid + 1;
                else hi = mid;
            }
            norm_run(data, out, s_scale, s_shift, r, lo, b, lane);
            r = lo;
            if (r < r1) b = bid[r];
        }
    }
}

// ---------------------------------------------------------------------------
extern "C" void kernel_launch(void* const* d_in, const int* in_sizes, int n_in,
                              void* d_out, int out_size) {
    const float* data = (const float*)d_in[0];
    const int* bid = (const int*)d_in[1];
    int N = in_sizes[0] / C;

    // Locate weights/bias among the remaining inputs (size-32 fp32 arrays).
    const float* w = nullptr;
    const float* bias = nullptr;
    for (int i = 2; i < n_in; ++i) {
        if (in_sizes[i] == C) {
            if (!w) w = (const float*)d_in[i];
            else if (!bias) bias = (const float*)d_in[i];
        }
    }

    const int threads = 256;

    // Reduce: single wave at 6 blocks/SM (48 warps/SM).
    {
        const int blocks = 148 * 6;
        int warps = blocks * (threads / 32);
        int rpw = (N + warps - 1) / warps;
        reduce_kernel<<<blocks, threads>>>(data, bid, N, rpw);
    }

    finalize_kernel<<<1, BMAX * C>>>(w, bias);

    // Normalize: single wave at 8 blocks/SM (R10-validated config).
    {
        const int blocks = 148 * 8;
        int warps = blocks * (threads / 32);
        int rpw = (N + warps - 1) / warps;
        normalize_kernel<<<blocks, threads>>>(data, bid, (float*)d_out,
                                              N, rpw);
    }
}

// round 13
// speedup vs baseline: 1.0154x; 1.0154x over previous
#include <cuda_runtime.h>

#define C 32
#define BMAX 16
#define EPS 1e-5f

// Scratch (device globals: zero-initialized at module load; finalize_kernel
// resets them after consuming, so every graph replay starts clean).
__device__ float g_sum[BMAX * C];
__device__ float g_sq[BMAX * C];
__device__ float g_cnt[BMAX];
__device__ float g_scale[BMAX * C];
__device__ float g_shift[BMAX * C];

// ---------------------------------------------------------------------------
// Warp-cooperative accumulation of one single-segment run [rs, re).
// Lane L loads the float4 at column (L&7), row offset (L>>3): a warp
// consumes 4 rows per LDG.128. 16-row main loop with one-iteration
// lookahead (4 LDG.128 prefetched while 4 are consumed). Empirics across
// R9/R11/R12: reduce BW tracks (warps/SM x pipeline depth); this round
// keeps depth 4 AND fits 5 blocks/SM via launch_bounds.
// ---------------------------------------------------------------------------
__device__ __forceinline__ void accum_run(const float* __restrict__ data,
                                          int rs, int re, int b, int lane) {
    int rows = re - rs;
    if (rows <= 0) return;
    int sub = lane & 7;        // float4 column (channels sub*4 .. sub*4+3)
    int rg  = lane >> 3;       // row offset within 4-row group

    const float4* base = reinterpret_cast<const float4*>(
        data + (size_t)rs * C) + (size_t)rg * 8 + sub;

    float4 s = make_float4(0.f, 0.f, 0.f, 0.f);
    float4 q = make_float4(0.f, 0.f, 0.f, 0.f);

    #define ACC(v)                                                   \
        s.x += (v).x; s.y += (v).y; s.z += (v).z; s.w += (v).w;      \
        q.x = fmaf((v).x, (v).x, q.x); q.y = fmaf((v).y, (v).y, q.y);\
        q.z = fmaf((v).z, (v).z, q.z); q.w = fmaf((v).w, (v).w, q.w)

    int nch = rows >> 4;               // full 16-row chunks
    int r = nch << 4;
    if (nch > 0) {
        float4 a0 = base[0];
        float4 a1 = base[32];
        float4 a2 = base[64];
        float4 a3 = base[96];
        for (int k = 1; k < nch; ++k) {
            const float4* p = base + (size_t)k * 128;
            float4 b0 = p[0];          // prefetch chunk k (4 loads batched)
            float4 b1 = p[32];
            float4 b2 = p[64];
            float4 b3 = p[96];
            ACC(a0); ACC(a1); ACC(a2); ACC(a3);
            a0 = b0; a1 = b1; a2 = b2; a3 = b3;
        }
        ACC(a0); ACC(a1); ACC(a2); ACC(a3);
    }
    for (; r + 4 <= rows; r += 4) {    // 0-3 remaining 4-row groups
        float4 a = base[(size_t)r * 8];
        ACC(a);
    }
    if (r < rows && r + rg < rows) {   // 1-3 remaining rows, predicated
        float4 a = base[(size_t)r * 8];
        ACC(a);
    }
    #undef ACC

    // Combine lanes sharing the same channels (rg = 0..3): xor 16, 8.
    #pragma unroll
    for (int off = 16; off >= 8; off >>= 1) {
        s.x += __shfl_xor_sync(0xffffffffu, s.x, off);
        s.y += __shfl_xor_sync(0xffffffffu, s.y, off);
        s.z += __shfl_xor_sync(0xffffffffu, s.z, off);
        s.w += __shfl_xor_sync(0xffffffffu, s.w, off);
        q.x += __shfl_xor_sync(0xffffffffu, q.x, off);
        q.y += __shfl_xor_sync(0xffffffffu, q.y, off);
        q.z += __shfl_xor_sync(0xffffffffu, q.z, off);
        q.w += __shfl_xor_sync(0xffffffffu, q.w, off);
    }

    if (rg == 0) {   // lanes 0..7 flush channels sub*4 .. sub*4+3
        int b4 = b * C + sub * 4;
        atomicAdd(&g_sum[b4 + 0], s.x);
        atomicAdd(&g_sum[b4 + 1], s.y);
        atomicAdd(&g_sum[b4 + 2], s.z);
        atomicAdd(&g_sum[b4 + 3], s.w);
        atomicAdd(&g_sq[b4 + 0], q.x);
        atomicAdd(&g_sq[b4 + 1], q.y);
        atomicAdd(&g_sq[b4 + 2], q.z);
        atomicAdd(&g_sq[b4 + 3], q.w);
    }
    if (lane == 0) atomicAdd(&g_cnt[b], (float)rows);
}

// ---------------------------------------------------------------------------
// Kernel 1: per-segment sum / sumsq / count.
// __launch_bounds__(256, 5): regs <= 51 so 5 blocks/SM (40 warps) fit,
// combined with the 4-deep pipeline -> ~160 LDG.128 in flight per SM.
// ---------------------------------------------------------------------------
__global__ void __launch_bounds__(256, 5)
reduce_kernel(const float* __restrict__ data,
              const int* __restrict__ bid,
              int N, int rows_per_warp) {
    int warp = (int)((blockIdx.x * blockDim.x + threadIdx.x) >> 5);
    int lane = threadIdx.x & 31;

    int r0 = warp * rows_per_warp;
    if (r0 >= N) return;
    int r1 = r0 + rows_per_warp;
    if (r1 > N) r1 = N;

    int b_first = bid[r0];
    int b_last = bid[r1 - 1];

    if (b_first == b_last) {
        accum_run(data, r0, r1, b_first, lane);
    } else {
        int r = r0;
        int b = b_first;
        while (r < r1) {
            int lo = r + 1, hi = r1;
            while (lo < hi) {                 // binary search run end
                int mid = (lo + hi) >> 1;     // broadcast load
                if (bid[mid] == b) lo = mid + 1;
                else hi = mid;
            }
            accum_run(data, r, lo, b, lane);
            r = lo;
            if (r < r1) b = bid[r];
        }
    }
}

// ---------------------------------------------------------------------------
// Kernel 2: fold stats into per-(b,c) scale/shift, THEN reset the
// accumulators to zero so the next graph replay starts clean.
// ---------------------------------------------------------------------------
__global__ void finalize_kernel(const float* __restrict__ w,
                                const float* __restrict__ bias) {
    int i = threadIdx.x;           // 0..BMAX*C-1
    if (i >= BMAX * C) return;
    int b = i / C, c = i % C;
    float cnt = g_cnt[b];
    float norm = 1.0f / (cnt + EPS);
    float sum = g_sum[i];
    float mean = sum * norm;
    float var = (g_sq[i] - 2.0f * mean * sum + mean * mean * cnt) * norm;
    float inv_std = rsqrtf(var + EPS);
    float wc = w ? w[c] : 1.0f;
    float bc = bias ? bias[c] : 0.0f;
    float sc = inv_std * wc;
    g_scale[i] = sc;
    g_shift[i] = bc - mean * sc;
    // Consume-and-reset for the next replay.
    g_sum[i] = 0.0f;
    g_sq[i] = 0.0f;
    if (c == 0) g_cnt[b] = 0.0f;
}

// ---------------------------------------------------------------------------
// Normalize one single-segment run [rs, re): scale/shift in registers
// (loaded once per run), inner loop pure LDG.128 -> FMA -> STG.128 with
// one-chunk lookahead.  [R10: 6.4 TB/s effective — at ceiling, unchanged]
// ---------------------------------------------------------------------------
__device__ __forceinline__ void norm_run(const float* __restrict__ data,
                                         float* __restrict__ out,
                                         const float4* s_scale,
                                         const float4* s_shift,
                                         int rs, int re, int b, int lane) {
    int rows = re - rs;
    if (rows <= 0) return;
    int sub = lane & 7;
    int rg  = lane >> 3;

    float4 sc = s_scale[b * 8 + sub];   // once per run
    float4 sh = s_shift[b * 8 + sub];

    const float4* pi = reinterpret_cast<const float4*>(
        data + (size_t)rs * C) + (size_t)rg * 8 + sub;
    float4* po = reinterpret_cast<float4*>(
        out + (size_t)rs * C) + (size_t)rg * 8 + sub;

    int nch = rows >> 3;               // full 8-row chunks
    int r = nch << 3;
    if (nch > 0) {
        float4 a = __ldcs(pi);
        float4 c = __ldcs(pi + 32);
        for (int k = 1; k < nch; ++k) {
            const float4* p = pi + (size_t)k * 64;
            float4 a2 = __ldcs(p);         // prefetch chunk k
            float4 c2 = __ldcs(p + 32);
            float4 o0, o1;
            o0.x = fmaf(a.x, sc.x, sh.x); o0.y = fmaf(a.y, sc.y, sh.y);
            o0.z = fmaf(a.z, sc.z, sh.z); o0.w = fmaf(a.w, sc.w, sh.w);
            o1.x = fmaf(c.x, sc.x, sh.x); o1.y = fmaf(c.y, sc.y, sh.y);
            o1.z = fmaf(c.z, sc.z, sh.z); o1.w = fmaf(c.w, sc.w, sh.w);
            float4* po_k = po + (size_t)(k - 1) * 64;
            __stcs(po_k, o0);
            __stcs(po_k + 32, o1);
            a = a2; c = c2;
        }
        float4 o0, o1;
        o0.x = fmaf(a.x, sc.x, sh.x); o0.y = fmaf(a.y, sc.y, sh.y);
        o0.z = fmaf(a.z, sc.z, sh.z); o0.w = fmaf(a.w, sc.w, sh.w);
        o1.x = fmaf(c.x, sc.x, sh.x); o1.y = fmaf(c.y, sc.y, sh.y);
        o1.z = fmaf(c.z, sc.z, sh.z); o1.w = fmaf(c.w, sc.w, sh.w);
        float4* po_k = po + (size_t)(nch - 1) * 64;
        __stcs(po_k, o0);
        __stcs(po_k + 32, o1);
    }
    if (r + 4 <= rows) {
        float4 a = __ldcs(pi + (size_t)r * 8);
        float4 o;
        o.x = fmaf(a.x, sc.x, sh.x); o.y = fmaf(a.y, sc.y, sh.y);
        o.z = fmaf(a.z, sc.z, sh.z); o.w = fmaf(a.w, sc.w, sh.w);
        __stcs(po + (size_t)r * 8, o);
        r += 4;
    }
    if (r < rows && r + rg < rows) {   // 1-3 remaining rows, predicated
        float4 a = __ldcs(pi + (size_t)r * 8);
        float4 o;
        o.x = fmaf(a.x, sc.x, sh.x); o.y = fmaf(a.y, sc.y, sh.y);
        o.z = fmaf(a.z, sc.z, sh.z); o.w = fmaf(a.w, sc.w, sh.w);
        __stcs(po + (size_t)r * 8, o);
    }
}

// ---------------------------------------------------------------------------
// Kernel 3: normalize, warp-chunked like the reduce.
// ---------------------------------------------------------------------------
__global__ void normalize_kernel(const float* __restrict__ data,
                                 const int* __restrict__ bid,
                                 float* __restrict__ out,
                                 int N, int rows_per_warp) {
    __shared__ float4 s_scale[BMAX * C / 4];
    __shared__ float4 s_shift[BMAX * C / 4];
    for (int i = threadIdx.x; i < BMAX * C / 4; i += blockDim.x) {
        s_scale[i] = reinterpret_cast<const float4*>(g_scale)[i];
        s_shift[i] = reinterpret_cast<const float4*>(g_shift)[i];
    }
    __syncthreads();

    int warp = (int)((blockIdx.x * blockDim.x + threadIdx.x) >> 5);
    int lane = threadIdx.x & 31;

    int r0 = warp * rows_per_warp;
    if (r0 >= N) return;
    int r1 = r0 + rows_per_warp;
    if (r1 > N) r1 = N;

    int b_first = bid[r0];
    int b_last = bid[r1 - 1];

    if (b_first == b_last) {
        norm_run(data, out, s_scale, s_shift, r0, r1, b_first, lane);
    } else {
        int r = r0;
        int b = b_first;
        while (r < r1) {
            int lo = r + 1, hi = r1;
            while (lo < hi) {
                int mid = (lo + hi) >> 1;     // broadcast load
                if (bid[mid] == b) lo = mid + 1;
                else hi = mid;
            }
            norm_run(data, out, s_scale, s_shift, r, lo, b, lane);
            r = lo;
            if (r < r1) b = bid[r];
        }
    }
}

// ---------------------------------------------------------------------------
extern "C" void kernel_launch(void* const* d_in, const int* in_sizes, int n_in,
                              void* d_out, int out_size) {
    const float* data = (const float*)d_in[0];
    const int* bid = (const int*)d_in[1];
    int N = in_sizes[0] / C;

    // Locate weights/bias among the remaining inputs (size-32 fp32 arrays).
    const float* w = nullptr;
    const float* bias = nullptr;
    for (int i = 2; i < n_in; ++i) {
        if (in_sizes[i] == C) {
            if (!w) w = (const float*)d_in[i];
            else if (!bias) bias = (const float*)d_in[i];
        }
    }

    const int threads = 256;

    // Reduce: single wave at 5 blocks/SM (40 warps/SM, 4-deep pipeline).
    {
        const int blocks = 148 * 5;
        int warps = blocks * (threads / 32);
        int rpw = (N + warps - 1) / warps;
        reduce_kernel<<<blocks, threads>>>(data, bid, N, rpw);
    }

    finalize_kernel<<<1, BMAX * C>>>(w, bias);

    // Normalize: single wave at 8 blocks/SM (R10-validated config).
    {
        const int blocks = 148 * 8;
        int warps = blocks * (threads / 32);
        int rpw = (N + warps - 1) / warps;
        normalize_kernel<<<blocks, threads>>>(data, bid, (float*)d_out,
                                              N, rpw);
    }
}